// round 7
// baseline (speedup 1.0000x reference)
#include <cuda_runtime.h>
#include <math.h>

#define BB   4
#define SS   1024
#define HIDC 768
#define HH   6
#define DD   64
#define AHC  384
#define KSC  9
#define PADC 4
#define OW   768   // output width = 2*AH
#define CKN  54    // H*KS
#define TIQ  32    // query rows per attention block
#define RPW  4     // query rows per warp (8 warps)
#define ATHR 256   // attention block threads
#define CKZ  6     // split-K factor for ck GEMM

typedef unsigned long long ull;

// ---------------- f32x2 packed helpers ----------------
__device__ __forceinline__ void ffma2(ull& d, ull a, ull b) {
    asm("fma.rn.f32x2 %0, %1, %2, %3;" : "=l"(d) : "l"(a), "l"(b), "l"(d));
}
__device__ __forceinline__ ull pack2(float lo, float hi) {
    ull r; asm("mov.b64 %0, {%1, %2};" : "=l"(r) : "f"(lo), "f"(hi)); return r;
}
__device__ __forceinline__ void unpack2(float& lo, float& hi, ull v) {
    asm("mov.b64 {%0, %1}, %2;" : "=f"(lo), "=f"(hi) : "l"(v));
}

// ---------------- scratch (device globals: no allocations allowed) ----------------
__device__ float g_mq [BB*SS*AHC];
__device__ float g_mk [BB*SS*AHC];
__device__ float g_mv [BB*SS*AHC];
__device__ float g_co [BB*SS*AHC];
__device__ float g_mkc[BB*SS*AHC];
__device__ float g_dwt[BB*SS*HIDC];
__device__ float g_ck [BB*SS*CKN];
__device__ float g_ckp[CKZ*BB*SS*CKN];   // split-K partials for ck logits
__device__ float g_tdsm[BB*SS];

// ---------------- GEMM core: C[M,N] = A[M,K] @ B (+bias), 128x64 tile, f32x2 ----------------
template<bool BT, bool BIAS, bool NGUARD, bool AMUL>
__device__ __forceinline__ void gemm_core(const float* __restrict__ A,
                                          const float* __restrict__ A2,
                                          const float* __restrict__ Bm,
                                          const float* __restrict__ bias,
                                          float* __restrict__ C,
                                          int N, int K, int m0, int n0,
                                          int kBeg, int kEnd)
{
    __shared__ float As[16][128];
    __shared__ float Bs[16][64];
    const int tid = threadIdx.x;
    const int ty = tid >> 4, tx = tid & 15;
    const int lr = tid >> 1, lk = (tid & 1) * 8;

    ull acc[8][2];
#pragma unroll
    for (int i = 0; i < 8; i++) { acc[i][0] = 0ull; acc[i][1] = 0ull; }

    for (int k0 = kBeg; k0 < kEnd; k0 += 16) {
        {
            const float* ap = A + (size_t)(m0 + lr) * K + k0 + lk;
            float4 a0 = *(const float4*)(ap);
            float4 a1 = *(const float4*)(ap + 4);
            if (AMUL) {
                const float* a2p = A2 + (size_t)(m0 + lr) * K + k0 + lk;
                float4 m0v = *(const float4*)(a2p);
                float4 m1v = *(const float4*)(a2p + 4);
                a0.x *= m0v.x; a0.y *= m0v.y; a0.z *= m0v.z; a0.w *= m0v.w;
                a1.x *= m1v.x; a1.y *= m1v.y; a1.z *= m1v.z; a1.w *= m1v.w;
            }
            As[lk + 0][lr] = a0.x; As[lk + 1][lr] = a0.y;
            As[lk + 2][lr] = a0.z; As[lk + 3][lr] = a0.w;
            As[lk + 4][lr] = a1.x; As[lk + 5][lr] = a1.y;
            As[lk + 6][lr] = a1.z; As[lk + 7][lr] = a1.w;
        }
        if (!BT) {
            int bk = tid >> 4, bn = (tid & 15) * 4;
            if (!NGUARD) {
                float4 bv = *(const float4*)(Bm + (size_t)(k0 + bk) * N + n0 + bn);
                Bs[bk][bn + 0] = bv.x; Bs[bk][bn + 1] = bv.y;
                Bs[bk][bn + 2] = bv.z; Bs[bk][bn + 3] = bv.w;
            } else {
#pragma unroll
                for (int j = 0; j < 4; j++) {
                    int n = n0 + bn + j;
                    Bs[bk][bn + j] = (n < N) ? Bm[(size_t)(k0 + bk) * N + n] : 0.f;
                }
            }
        } else {
            int bn = tid >> 2, bkk = (tid & 3) * 4;
            float4 bv = *(const float4*)(Bm + (size_t)(n0 + bn) * K + k0 + bkk);
            Bs[bkk + 0][bn] = bv.x; Bs[bkk + 1][bn] = bv.y;
            Bs[bkk + 2][bn] = bv.z; Bs[bkk + 3][bn] = bv.w;
        }
        __syncthreads();
#pragma unroll
        for (int k = 0; k < 16; k++) {
            float4 aA = *(const float4*)&As[k][ty * 8];
            float4 aB = *(const float4*)&As[k][ty * 8 + 4];
            ull b01 = *(const ull*)&Bs[k][tx * 4];
            ull b23 = *(const ull*)&Bs[k][tx * 4 + 2];
            ull ap;
            ap = pack2(aA.x, aA.x); ffma2(acc[0][0], ap, b01); ffma2(acc[0][1], ap, b23);
            ap = pack2(aA.y, aA.y); ffma2(acc[1][0], ap, b01); ffma2(acc[1][1], ap, b23);
            ap = pack2(aA.z, aA.z); ffma2(acc[2][0], ap, b01); ffma2(acc[2][1], ap, b23);
            ap = pack2(aA.w, aA.w); ffma2(acc[3][0], ap, b01); ffma2(acc[3][1], ap, b23);
            ap = pack2(aB.x, aB.x); ffma2(acc[4][0], ap, b01); ffma2(acc[4][1], ap, b23);
            ap = pack2(aB.y, aB.y); ffma2(acc[5][0], ap, b01); ffma2(acc[5][1], ap, b23);
            ap = pack2(aB.z, aB.z); ffma2(acc[6][0], ap, b01); ffma2(acc[6][1], ap, b23);
            ap = pack2(aB.w, aB.w); ffma2(acc[7][0], ap, b01); ffma2(acc[7][1], ap, b23);
        }
        __syncthreads();
    }
#pragma unroll
    for (int i = 0; i < 8; i++) {
        int m = m0 + ty * 8 + i;
#pragma unroll
        for (int p = 0; p < 2; p++) {
            float lo, hi; unpack2(lo, hi, acc[i][p]);
            int n = n0 + tx * 4 + 2 * p;
            if (!NGUARD || n < N) {
                float v = lo; if (BIAS) v += bias[n];
                C[(size_t)m * N + n] = v;
            }
            if (!NGUARD || n + 1 < N) {
                float v = hi; if (BIAS) v += bias[n + 1];
                C[(size_t)m * N + n + 1] = v;
            }
        }
    }
}

// fused 4-way projection GEMM: z selects (A, B, bias, C)
__global__ void __launch_bounds__(256) gemm_fused(const float* __restrict__ Q,
                                                  const float* __restrict__ Kin,
                                                  const float* __restrict__ V,
                                                  const float* __restrict__ Wq,
                                                  const float* __restrict__ Wk,
                                                  const float* __restrict__ Wv,
                                                  const float* __restrict__ coW,
                                                  const float* __restrict__ cob,
                                                  float* __restrict__ mq,
                                                  float* __restrict__ mk,
                                                  float* __restrict__ mv,
                                                  float* __restrict__ co)
{
    int m0 = blockIdx.x * 128, n0 = blockIdx.y * 64;
    switch (blockIdx.z) {
    case 0: gemm_core<false,false,false,false>(Q,   nullptr, Wq,  nullptr, mq, AHC, HIDC, m0, n0, 0, HIDC); break;
    case 1: gemm_core<false,false,false,false>(Kin, nullptr, Wk,  nullptr, mk, AHC, HIDC, m0, n0, 0, HIDC); break;
    case 2: gemm_core<false,false,false,false>(V,   nullptr, Wv,  nullptr, mv, AHC, HIDC, m0, n0, 0, HIDC); break;
    default:gemm_core<false,true, false,false>(V,   nullptr, coW, cob,     co, AHC, HIDC, m0, n0, 0, HIDC); break;
    }
}

// pointwise conv GEMM: mkc = dwt @ pw_w^T + sep_b
__global__ void __launch_bounds__(256) gemm_pw(const float* __restrict__ dwt,
                                               const float* __restrict__ pw,
                                               const float* __restrict__ sb,
                                               float* __restrict__ mkc)
{
    gemm_core<true, true, false, false>(dwt, nullptr, pw, sb, mkc,
                                        AHC, HIDC, blockIdx.x * 128, blockIdx.y * 64, 0, HIDC);
}

// ck logits GEMM, split-K x CKZ
__global__ void __launch_bounds__(256) gemm_ck(const float* __restrict__ mkc,
                                               const float* __restrict__ mq,
                                               const float* __restrict__ ckW,
                                               const float* __restrict__ ckb,
                                               float* __restrict__ ckp)
{
    int z = blockIdx.z;
    const int KS_ = AHC / CKZ;   // 64
    float* Cz = ckp + (size_t)z * (BB * SS * CKN);
    if (z == 0)
        gemm_core<false, true,  true, true>(mkc, mq, ckW, ckb, Cz,
                                            CKN, AHC, blockIdx.x * 128, 0, 0, KS_);
    else
        gemm_core<false, false, true, true>(mkc, mq, ckW, nullptr, Cz,
                                            CKN, AHC, blockIdx.x * 128, 0, z * KS_, z * KS_ + KS_);
}

// ck: sum CKZ partials, softmax over KS=9, write g_ck
__global__ void __launch_bounds__(256) cksm_kernel()
{
    int row = blockIdx.x * 256 + threadIdx.x;     // BB*SS*HH rows
    if (row >= BB * SS * HH) return;
    const size_t R = (size_t)BB * SS * CKN;
    const float* p0 = g_ckp + (size_t)row * KSC;
    float v[KSC];
    float m = -3e38f;
#pragma unroll
    for (int k = 0; k < KSC; k++) {
        float s = 0.f;
#pragma unroll
        for (int z = 0; z < CKZ; z++) s += p0[z * R + k];
        v[k] = s;
        m = fmaxf(m, s);
    }
    float sum = 0.f;
#pragma unroll
    for (int k = 0; k < KSC; k++) { v[k] = expf(v[k] - m); sum += v[k]; }
    float invs = 1.f / sum;
    float* o = g_ck + (size_t)row * KSC;
#pragma unroll
    for (int k = 0; k < KSC; k++) o[k] = v[k] * invs;
}

// ---------------- depthwise conv over sequence (kernel 9, pad 4) ----------------
__global__ void __launch_bounds__(256) dw_kernel(const float* __restrict__ Kin,
                                                 const float* __restrict__ dw_w)
{
    int bs = blockIdx.x;              // b*S + s
    int b = bs >> 10, s = bs & 1023;
    for (int c = threadIdx.x; c < HIDC; c += 256) {
        float acc = 0.f;
#pragma unroll
        for (int k = 0; k < KSC; k++) {
            int sr = s + k - PADC;
            if (sr >= 0 && sr < SS)
                acc += Kin[(size_t)(b * SS + sr) * HIDC + c] * dw_w[c * KSC + k];
        }
        g_dwt[(size_t)bs * HIDC + c] = acc;
    }
}

// ---------------- conv_out: sliding-window gather of co weighted by ck ----------------
__global__ void __launch_bounds__(128) conv_out_kernel(float* __restrict__ out)
{
    int bs = blockIdx.x;
    int b = bs >> 10, s = bs & 1023;
    __shared__ float cks[CKN];
    if (threadIdx.x < CKN) cks[threadIdx.x] = g_ck[(size_t)bs * CKN + threadIdx.x];
    __syncthreads();
    for (int a = threadIdx.x; a < AHC; a += 128) {
        int h = a >> 6;
        float acc = 0.f;
#pragma unroll
        for (int k = 0; k < KSC; k++) {
            int sr = s + k - PADC;
            if (sr >= 0 && sr < SS)
                acc += g_co[(size_t)(b * SS + sr) * AHC + a] * cks[h * KSC + k];
        }
        out[(size_t)bs * OW + AHC + a] = acc;
    }
}

// ---------------- td softmax (independent of head and query row) ----------------
__global__ void __launch_bounds__(256) tdsm_kernel(const float* __restrict__ td,
                                                   const int* __restrict__ mask)
{
    __shared__ float red[8];
    __shared__ float bc;
    int b = blockIdx.x, tid = threadIdx.x;
    int wid = tid >> 5, ln = tid & 31;

    float ss = 0.f;
    for (int j = tid; j < SS; j += 256) { float v = td[b * SS + j]; ss += v * v; }
#pragma unroll
    for (int o = 16; o; o >>= 1) ss += __shfl_xor_sync(0xffffffffu, ss, o);
    if (ln == 0) red[wid] = ss;
    __syncthreads();
    if (tid == 0) {
        float t = 0.f;
        for (int k = 0; k < 8; k++) t += red[k];
        bc = 1.f / fmaxf(sqrtf(t), 1e-12f);
    }
    __syncthreads();
    float inv = bc;

    float m = -1e4f;
    for (int j = tid; j < SS; j += 256)
        if (mask[b * SS + j]) m = fmaxf(m, td[b * SS + j] * inv);
#pragma unroll
    for (int o = 16; o; o >>= 1) m = fmaxf(m, __shfl_xor_sync(0xffffffffu, m, o));
    if (ln == 0) red[wid] = m;
    __syncthreads();
    if (tid == 0) {
        float t = -1e4f;
        for (int k = 0; k < 8; k++) t = fmaxf(t, red[k]);
        bc = t;
    }
    __syncthreads();
    float mm = bc;
    __syncthreads();

    float den = 0.f;
    for (int j = tid; j < SS; j += 256)
        if (mask[b * SS + j]) den += expf(td[b * SS + j] * inv - mm);
#pragma unroll
    for (int o = 16; o; o >>= 1) den += __shfl_xor_sync(0xffffffffu, den, o);
    if (ln == 0) red[wid] = den;
    __syncthreads();
    if (tid == 0) {
        float t = 0.f;
        for (int k = 0; k < 8; k++) t += red[k];
        bc = 1.f / t;
    }
    __syncthreads();
    float invden = bc;

    for (int j = tid; j < SS; j += 256) {
        float v = mask[b * SS + j] ? expf(td[b * SS + j] * inv - mm) * invden : 0.f;
        g_tdsm[b * SS + j] = v;
    }
}

// ---------------- attention with distance decay ----------------
// grid (S/32, H, B); 8 warps x 4 query rows each. K/V in 128x66 smem.
// Probs quad-packed: scw[sidx*4+rr] -> PV fetches 4 rows with one uniform
// LDS.128. Mask bitmask; tds bit-transposed. Score passes register-resident.
__global__ void __launch_bounds__(ATHR, 1) attn_kernel(const int* __restrict__ mask,
                                                       const float* __restrict__ gammas,
                                                       float* __restrict__ out)
{
    extern __shared__ float sm[];
    float* kt   = sm;                        // 128*66 = 8448
    float* scp  = kt + 128 * 66;             // 8 warps * 4224 = 33792
    float* qs   = scp + 8 * 4224;            // 32*64 = 2048
    float* tdsT = qs + TIQ * 64;             // 1024 (bit-transposed)
    unsigned* mbits = (unsigned*)(tdsT + 1024);  // 32 words

    const int tid  = threadIdx.x;
    const int w    = tid >> 5, lane = tid & 31;
    const int i0   = blockIdx.x * TIQ;
    const int h    = blockIdx.y;
    const int b    = blockIdx.z;
    const int r0   = w * RPW;

    // mask bits via ballot
    for (int base = tid; base < SS; base += ATHR) {
        int mv = mask[b * SS + base];
        unsigned bal = __ballot_sync(0xffffffffu, mv != 0);
        if (lane == 0) mbits[base >> 5] = bal;
    }
    // tds bit-transposed: tdsT[(j&31)<<5 | j>>5] = tdsm[j]
    for (int j = tid; j < SS; j += ATHR)
        tdsT[((j & 31) << 5) | (j >> 5)] = g_tdsm[b * SS + j];
    for (int idx = tid; idx < TIQ * 32; idx += ATHR) {
        int r = idx >> 5, dp = idx & 31;
        *(float2*)&qs[r * 64 + 2 * dp] =
            *(const float2*)(g_mq + (size_t)(b * SS + i0 + r) * AHC + h * DD + 2 * dp);
    }
    float gv = gammas[h];
    float gamma = -(gv > 20.f ? gv : log1pf(expf(gv)));   // -softplus

    float* scw = scp + w * 4224;

    // ---- QK: scores for 4 rows x 128 j per warp per tile ----
    for (int jt = 0; jt < 8; jt++) {
        __syncthreads();
        for (int idx = tid; idx < 4096; idx += ATHR) {
            int r = idx >> 5, dp = idx & 31;
            *(float2*)&kt[r * 66 + 2 * dp] =
                *(const float2*)(g_mk + (size_t)(b * SS + jt * 128 + r) * AHC + h * DD + 2 * dp);
        }
        __syncthreads();
        ull acc[RPW][4];
#pragma unroll
        for (int rr = 0; rr < RPW; rr++)
#pragma unroll
            for (int c = 0; c < 4; c++) acc[rr][c] = 0ull;
#pragma unroll
        for (int dp = 0; dp < 32; dp++) {
            ull k0 = *(const ull*)&kt[(lane      ) * 66 + 2 * dp];
            ull k1 = *(const ull*)&kt[(lane +  32) * 66 + 2 * dp];
            ull k2 = *(const ull*)&kt[(lane +  64) * 66 + 2 * dp];
            ull k3 = *(const ull*)&kt[(lane +  96) * 66 + 2 * dp];
#pragma unroll
            for (int rr = 0; rr < RPW; rr++) {
                ull q2 = *(const ull*)&qs[(r0 + rr) * 64 + 2 * dp];
                ffma2(acc[rr][0], q2, k0);
                ffma2(acc[rr][1], q2, k1);
                ffma2(acc[rr][2], q2, k2);
                ffma2(acc[rr][3], q2, k3);
            }
        }
#pragma unroll
        for (int rr = 0; rr < RPW; rr++) {
#pragma unroll
            for (int c = 0; c < 4; c++) {
                float lo, hi; unpack2(lo, hi, acc[rr][c]);
                int j = jt * 128 + c * 32 + lane;
                scw[(j + (j >> 5)) * 4 + rr] = (lo + hi) * 0.125f;
            }
        }
    }
    __syncwarp();

    // ---- softmax / distance-decay, register-resident; j = lane*32+c ----
    const unsigned mrow = mbits[lane];
    float invsv[RPW];
#pragma unroll
    for (int rr = 0; rr < RPW; rr++) {
        const int i = i0 + r0 + rr;
        float sv[32];
#pragma unroll
        for (int c = 0; c < 32; c++) sv[c] = scw[(lane * 33 + c) * 4 + rr];

        // pass 1: masked max
        float m1 = -3e38f;
#pragma unroll
        for (int c = 0; c < 32; c++)
            if ((mrow >> c) & 1) m1 = fmaxf(m1, sv[c]);
#pragma unroll
        for (int o = 16; o; o >>= 1) m1 = fmaxf(m1, __shfl_xor_sync(0xffffffffu, m1, o));

        // pass 2: p ~ exp * mask, inclusive cumsum
        float cuml[32];
        float run = 0.f;
#pragma unroll
        for (int c = 0; c < 32; c++) {
            float p = ((mrow >> c) & 1) ? expf(sv[c] - m1) : 0.f;
            run += p;
            cuml[c] = run;
        }
        float v = run;
#pragma unroll
        for (int o = 1; o < 32; o <<= 1) {
            float t = __shfl_up_sync(0xffffffffu, v, o);
            if (lane >= o) v += t;
        }
        float total = __shfl_sync(0xffffffffu, v, 31);
        float off = v - run;
        float invtot = 1.f / fmaxf(total, 1e-30f);

        // pass 3: total_effect, modified scores, max
        float m2 = -3e38f;
#pragma unroll
        for (int c = 0; c < 32; c++) {
            int j = lane * 32 + c;
            float s2;
            if ((mrow >> c) & 1) {
                float cum = cuml[c] + off;
                float pos = fabsf((float)(j - i));
                float rem = (total - cum) * invtot;
                float ds = sqrtf(fmaxf(rem * pos, 0.f));
                float te = expf(gamma * ds);
                te = fminf(fmaxf(te, 1e-5f), 1e5f);
                if (j < i) te -= tdsT[(c << 5) | lane];
                s2 = sv[c] * te;
            } else {
                s2 = -1e8f;
            }
            sv[c] = s2;
            m2 = fmaxf(m2, s2);
        }
#pragma unroll
        for (int o = 16; o; o >>= 1) m2 = fmaxf(m2, __shfl_xor_sync(0xffffffffu, m2, o));

        // pass 4: exp + sum, store quad-packed
        float sum2 = 0.f;
#pragma unroll
        for (int c = 0; c < 32; c++) {
            float e = expf(sv[c] - m2);
            scw[(lane * 33 + c) * 4 + rr] = e;
            sum2 += e;
        }
#pragma unroll
        for (int o = 16; o; o >>= 1) sum2 += __shfl_xor_sync(0xffffffffu, sum2, o);
        invsv[rr] = 1.f / sum2;
    }

    // ---- PV: lane owns d-pair; 4 rows' probs via one uniform LDS.128 ----
    ull acc0 = 0ull, acc1 = 0ull, acc2 = 0ull, acc3 = 0ull;
    for (int jt = 0; jt < 8; jt++) {
        __syncthreads();
        for (int idx = tid; idx < 4096; idx += ATHR) {
            int r = idx >> 5, dp = idx & 31;
            *(float2*)&kt[r * 66 + 2 * dp] =
                *(const float2*)(g_mv + (size_t)(b * SS + jt * 128 + r) * AHC + h * DD + 2 * dp);
        }
        __syncthreads();
        int jb = jt * 128;
#pragma unroll 8
        for (int jl = 0; jl < 128; jl++) {
            int j = jb + jl;
            float4 pr = *(const float4*)&scw[(j + (j >> 5)) * 4];
            ull kv = *(const ull*)&kt[jl * 66 + 2 * lane];
            ffma2(acc0, pack2(pr.x, pr.x), kv);
            ffma2(acc1, pack2(pr.y, pr.y), kv);
            ffma2(acc2, pack2(pr.z, pr.z), kv);
            ffma2(acc3, pack2(pr.w, pr.w), kv);
        }
    }
    {
        float lo, hi;
        size_t ob = (size_t)(b * SS + i0 + r0) * OW + h * DD;
        unpack2(lo, hi, acc0);
        *(float2*)(out + ob + 2 * lane) = make_float2(lo * invsv[0], hi * invsv[0]);
        unpack2(lo, hi, acc1); ob += OW;
        *(float2*)(out + ob + 2 * lane) = make_float2(lo * invsv[1], hi * invsv[1]);
        unpack2(lo, hi, acc2); ob += OW;
        *(float2*)(out + ob + 2 * lane) = make_float2(lo * invsv[2], hi * invsv[2]);
        unpack2(lo, hi, acc3); ob += OW;
        *(float2*)(out + ob + 2 * lane) = make_float2(lo * invsv[3], hi * invsv[3]);
    }
}

// ---------------- launch ----------------
extern "C" void kernel_launch(void* const* d_in, const int* in_sizes, int n_in,
                              void* d_out, int out_size)
{
    const float* Q      = (const float*)d_in[0];
    const float* Kin    = (const float*)d_in[1];
    const float* V      = (const float*)d_in[2];
    const float* td     = (const float*)d_in[3];
    const int*   mask   = (const int*)  d_in[4];
    const float* Wq     = (const float*)d_in[5];
    const float* Wk     = (const float*)d_in[6];
    const float* Wv     = (const float*)d_in[7];
    const float* dw_w   = (const float*)d_in[8];
    const float* pw_w   = (const float*)d_in[9];
    const float* sep_b  = (const float*)d_in[10];
    const float* ck_W   = (const float*)d_in[11];
    const float* ck_b   = (const float*)d_in[12];
    const float* co_W   = (const float*)d_in[13];
    const float* co_b   = (const float*)d_in[14];
    const float* gammas = (const float*)d_in[15];
    float* out = (float*)d_out;

    float *p_mq, *p_mk, *p_mv, *p_co, *p_mkc, *p_dwt, *p_ckp;
    cudaGetSymbolAddress((void**)&p_mq,  g_mq);
    cudaGetSymbolAddress((void**)&p_mk,  g_mk);
    cudaGetSymbolAddress((void**)&p_mv,  g_mv);
    cudaGetSymbolAddress((void**)&p_co,  g_co);
    cudaGetSymbolAddress((void**)&p_mkc, g_mkc);
    cudaGetSymbolAddress((void**)&p_dwt, g_dwt);
    cudaGetSymbolAddress((void**)&p_ckp, g_ckp);

    const int M = BB * SS;

    // launch order arranged so attn_kernel is the 4th launch (ncu captures #4)
    tdsm_kernel<<<BB, 256>>>(td, mask);                                             // 1
    gemm_fused<<<dim3(M / 128, AHC / 64, 4), 256>>>(Q, Kin, V, Wq, Wk, Wv,          // 2
                                                    co_W, co_b, p_mq, p_mk, p_mv, p_co);
    dw_kernel<<<BB * SS, 256>>>(Kin, dw_w);                                         // 3

    int smem = (128 * 66 + 8 * 4224 + TIQ * 64 + 1024 + 32) * (int)sizeof(float);
    cudaFuncSetAttribute(attn_kernel, cudaFuncAttributeMaxDynamicSharedMemorySize, smem);
    attn_kernel<<<dim3(SS / TIQ, HH, BB), ATHR, smem>>>(mask, gammas, out);         // 4

    gemm_pw<<<dim3(M / 128, AHC / 64), 256>>>(p_dwt, pw_w, sep_b, p_mkc);           // 5
    gemm_ck<<<dim3(M / 128, 1, CKZ), 256>>>(p_mkc, p_mq, ck_W, ck_b, p_ckp);        // 6
    cksm_kernel<<<(BB * SS * HH + 255) / 256, 256>>>();                             // 7
    conv_out_kernel<<<BB * SS, 128>>>(out);                                         // 8
}

// round 8
// speedup vs baseline: 1.2097x; 1.2097x over previous
#include <cuda_runtime.h>
#include <math.h>

#define BB   4
#define SS   1024
#define HIDC 768
#define HH   6
#define DD   64
#define AHC  384
#define KSC  9
#define PADC 4
#define OW   768   // output width = 2*AH
#define CKN  54    // H*KS
#define TIQ  16    // query rows per attention block
#define ATHR 256   // attention block threads (8 warps)
#define CKZ  6     // split-K factor for ck GEMM

typedef unsigned long long ull;

// ---------------- f32x2 packed helpers ----------------
__device__ __forceinline__ void ffma2(ull& d, ull a, ull b) {
    asm("fma.rn.f32x2 %0, %1, %2, %3;" : "=l"(d) : "l"(a), "l"(b), "l"(d));
}
__device__ __forceinline__ ull pack2(float lo, float hi) {
    ull r; asm("mov.b64 %0, {%1, %2};" : "=l"(r) : "f"(lo), "f"(hi)); return r;
}
__device__ __forceinline__ void unpack2(float& lo, float& hi, ull v) {
    asm("mov.b64 {%0, %1}, %2;" : "=f"(lo), "=f"(hi) : "l"(v));
}

// ---------------- scratch (device globals: no allocations allowed) ----------------
__device__ float g_mq [BB*SS*AHC];
__device__ float g_mk [BB*SS*AHC];
__device__ float g_mv [BB*SS*AHC];
__device__ float g_co [BB*SS*AHC];
__device__ float g_mkc[BB*SS*AHC];
__device__ float g_dwt[BB*SS*HIDC];
__device__ float g_ck [BB*SS*CKN];
__device__ float g_ckp[CKZ*BB*SS*CKN];   // split-K partials for ck logits
__device__ float g_tdsm[BB*SS];

// ---------------- GEMM core: C[M,N] = A[M,K] @ B (+bias), 128x64 tile, f32x2 ----------------
template<bool BT, bool BIAS, bool NGUARD, bool AMUL>
__device__ __forceinline__ void gemm_core(const float* __restrict__ A,
                                          const float* __restrict__ A2,
                                          const float* __restrict__ Bm,
                                          const float* __restrict__ bias,
                                          float* __restrict__ C,
                                          int N, int K, int m0, int n0,
                                          int kBeg, int kEnd)
{
    __shared__ float As[16][128];
    __shared__ float Bs[16][64];
    const int tid = threadIdx.x;
    const int ty = tid >> 4, tx = tid & 15;
    const int lr = tid >> 1, lk = (tid & 1) * 8;

    ull acc[8][2];
#pragma unroll
    for (int i = 0; i < 8; i++) { acc[i][0] = 0ull; acc[i][1] = 0ull; }

    for (int k0 = kBeg; k0 < kEnd; k0 += 16) {
        {
            const float* ap = A + (size_t)(m0 + lr) * K + k0 + lk;
            float4 a0 = *(const float4*)(ap);
            float4 a1 = *(const float4*)(ap + 4);
            if (AMUL) {
                const float* a2p = A2 + (size_t)(m0 + lr) * K + k0 + lk;
                float4 m0v = *(const float4*)(a2p);
                float4 m1v = *(const float4*)(a2p + 4);
                a0.x *= m0v.x; a0.y *= m0v.y; a0.z *= m0v.z; a0.w *= m0v.w;
                a1.x *= m1v.x; a1.y *= m1v.y; a1.z *= m1v.z; a1.w *= m1v.w;
            }
            As[lk + 0][lr] = a0.x; As[lk + 1][lr] = a0.y;
            As[lk + 2][lr] = a0.z; As[lk + 3][lr] = a0.w;
            As[lk + 4][lr] = a1.x; As[lk + 5][lr] = a1.y;
            As[lk + 6][lr] = a1.z; As[lk + 7][lr] = a1.w;
        }
        if (!BT) {
            int bk = tid >> 4, bn = (tid & 15) * 4;
            if (!NGUARD) {
                float4 bv = *(const float4*)(Bm + (size_t)(k0 + bk) * N + n0 + bn);
                Bs[bk][bn + 0] = bv.x; Bs[bk][bn + 1] = bv.y;
                Bs[bk][bn + 2] = bv.z; Bs[bk][bn + 3] = bv.w;
            } else {
#pragma unroll
                for (int j = 0; j < 4; j++) {
                    int n = n0 + bn + j;
                    Bs[bk][bn + j] = (n < N) ? Bm[(size_t)(k0 + bk) * N + n] : 0.f;
                }
            }
        } else {
            int bn = tid >> 2, bkk = (tid & 3) * 4;
            float4 bv = *(const float4*)(Bm + (size_t)(n0 + bn) * K + k0 + bkk);
            Bs[bkk + 0][bn] = bv.x; Bs[bkk + 1][bn] = bv.y;
            Bs[bkk + 2][bn] = bv.z; Bs[bkk + 3][bn] = bv.w;
        }
        __syncthreads();
#pragma unroll
        for (int k = 0; k < 16; k++) {
            float4 aA = *(const float4*)&As[k][ty * 8];
            float4 aB = *(const float4*)&As[k][ty * 8 + 4];
            ull b01 = *(const ull*)&Bs[k][tx * 4];
            ull b23 = *(const ull*)&Bs[k][tx * 4 + 2];
            ull ap;
            ap = pack2(aA.x, aA.x); ffma2(acc[0][0], ap, b01); ffma2(acc[0][1], ap, b23);
            ap = pack2(aA.y, aA.y); ffma2(acc[1][0], ap, b01); ffma2(acc[1][1], ap, b23);
            ap = pack2(aA.z, aA.z); ffma2(acc[2][0], ap, b01); ffma2(acc[2][1], ap, b23);
            ap = pack2(aA.w, aA.w); ffma2(acc[3][0], ap, b01); ffma2(acc[3][1], ap, b23);
            ap = pack2(aB.x, aB.x); ffma2(acc[4][0], ap, b01); ffma2(acc[4][1], ap, b23);
            ap = pack2(aB.y, aB.y); ffma2(acc[5][0], ap, b01); ffma2(acc[5][1], ap, b23);
            ap = pack2(aB.z, aB.z); ffma2(acc[6][0], ap, b01); ffma2(acc[6][1], ap, b23);
            ap = pack2(aB.w, aB.w); ffma2(acc[7][0], ap, b01); ffma2(acc[7][1], ap, b23);
        }
        __syncthreads();
    }
#pragma unroll
    for (int i = 0; i < 8; i++) {
        int m = m0 + ty * 8 + i;
#pragma unroll
        for (int p = 0; p < 2; p++) {
            float lo, hi; unpack2(lo, hi, acc[i][p]);
            int n = n0 + tx * 4 + 2 * p;
            if (!NGUARD || n < N) {
                float v = lo; if (BIAS) v += bias[n];
                C[(size_t)m * N + n] = v;
            }
            if (!NGUARD || n + 1 < N) {
                float v = hi; if (BIAS) v += bias[n + 1];
                C[(size_t)m * N + n + 1] = v;
            }
        }
    }
}

// fused 4-way projection GEMM: z selects (A, B, bias, C)
__global__ void __launch_bounds__(256) gemm_fused(const float* __restrict__ Q,
                                                  const float* __restrict__ Kin,
                                                  const float* __restrict__ V,
                                                  const float* __restrict__ Wq,
                                                  const float* __restrict__ Wk,
                                                  const float* __restrict__ Wv,
                                                  const float* __restrict__ coW,
                                                  const float* __restrict__ cob,
                                                  float* __restrict__ mq,
                                                  float* __restrict__ mk,
                                                  float* __restrict__ mv,
                                                  float* __restrict__ co)
{
    int m0 = blockIdx.x * 128, n0 = blockIdx.y * 64;
    switch (blockIdx.z) {
    case 0: gemm_core<false,false,false,false>(Q,   nullptr, Wq,  nullptr, mq, AHC, HIDC, m0, n0, 0, HIDC); break;
    case 1: gemm_core<false,false,false,false>(Kin, nullptr, Wk,  nullptr, mk, AHC, HIDC, m0, n0, 0, HIDC); break;
    case 2: gemm_core<false,false,false,false>(V,   nullptr, Wv,  nullptr, mv, AHC, HIDC, m0, n0, 0, HIDC); break;
    default:gemm_core<false,true, false,false>(V,   nullptr, coW, cob,     co, AHC, HIDC, m0, n0, 0, HIDC); break;
    }
}

// pointwise conv GEMM: mkc = dwt @ pw_w^T + sep_b
__global__ void __launch_bounds__(256) gemm_pw(const float* __restrict__ dwt,
                                               const float* __restrict__ pw,
                                               const float* __restrict__ sb,
                                               float* __restrict__ mkc)
{
    gemm_core<true, true, false, false>(dwt, nullptr, pw, sb, mkc,
                                        AHC, HIDC, blockIdx.x * 128, blockIdx.y * 64, 0, HIDC);
}

// ck logits GEMM, split-K x CKZ
__global__ void __launch_bounds__(256) gemm_ck(const float* __restrict__ mkc,
                                               const float* __restrict__ mq,
                                               const float* __restrict__ ckW,
                                               const float* __restrict__ ckb,
                                               float* __restrict__ ckp)
{
    int z = blockIdx.z;
    const int KS_ = AHC / CKZ;   // 64
    float* Cz = ckp + (size_t)z * (BB * SS * CKN);
    if (z == 0)
        gemm_core<false, true,  true, true>(mkc, mq, ckW, ckb, Cz,
                                            CKN, AHC, blockIdx.x * 128, 0, 0, KS_);
    else
        gemm_core<false, false, true, true>(mkc, mq, ckW, nullptr, Cz,
                                            CKN, AHC, blockIdx.x * 128, 0, z * KS_, z * KS_ + KS_);
}

// ck: sum CKZ partials, softmax over KS=9, write g_ck
__global__ void __launch_bounds__(256) cksm_kernel()
{
    int row = blockIdx.x * 256 + threadIdx.x;     // BB*SS*HH rows
    if (row >= BB * SS * HH) return;
    const size_t R = (size_t)BB * SS * CKN;
    const float* p0 = g_ckp + (size_t)row * KSC;
    float v[KSC];
    float m = -3e38f;
#pragma unroll
    for (int k = 0; k < KSC; k++) {
        float s = 0.f;
#pragma unroll
        for (int z = 0; z < CKZ; z++) s += p0[z * R + k];
        v[k] = s;
        m = fmaxf(m, s);
    }
    float sum = 0.f;
#pragma unroll
    for (int k = 0; k < KSC; k++) { v[k] = expf(v[k] - m); sum += v[k]; }
    float invs = 1.f / sum;
    float* o = g_ck + (size_t)row * KSC;
#pragma unroll
    for (int k = 0; k < KSC; k++) o[k] = v[k] * invs;
}

// ---------------- depthwise conv over sequence (kernel 9, pad 4) ----------------
__global__ void __launch_bounds__(256) dw_kernel(const float* __restrict__ Kin,
                                                 const float* __restrict__ dw_w)
{
    int bs = blockIdx.x;              // b*S + s
    int b = bs >> 10, s = bs & 1023;
    for (int c = threadIdx.x; c < HIDC; c += 256) {
        float acc = 0.f;
#pragma unroll
        for (int k = 0; k < KSC; k++) {
            int sr = s + k - PADC;
            if (sr >= 0 && sr < SS)
                acc += Kin[(size_t)(b * SS + sr) * HIDC + c] * dw_w[c * KSC + k];
        }
        g_dwt[(size_t)bs * HIDC + c] = acc;
    }
}

// ---------------- conv_out: sliding-window gather of co weighted by ck ----------------
__global__ void __launch_bounds__(128) conv_out_kernel(float* __restrict__ out)
{
    int bs = blockIdx.x;
    int b = bs >> 10, s = bs & 1023;
    __shared__ float cks[CKN];
    if (threadIdx.x < CKN) cks[threadIdx.x] = g_ck[(size_t)bs * CKN + threadIdx.x];
    __syncthreads();
    for (int a = threadIdx.x; a < AHC; a += 128) {
        int h = a >> 6;
        float acc = 0.f;
#pragma unroll
        for (int k = 0; k < KSC; k++) {
            int sr = s + k - PADC;
            if (sr >= 0 && sr < SS)
                acc += g_co[(size_t)(b * SS + sr) * AHC + a] * cks[h * KSC + k];
        }
        out[(size_t)bs * OW + AHC + a] = acc;
    }
}

// ---------------- td softmax (independent of head and query row) ----------------
__global__ void __launch_bounds__(256) tdsm_kernel(const float* __restrict__ td,
                                                   const int* __restrict__ mask)
{
    __shared__ float red[8];
    __shared__ float bc;
    int b = blockIdx.x, tid = threadIdx.x;
    int wid = tid >> 5, ln = tid & 31;

    float ss = 0.f;
    for (int j = tid; j < SS; j += 256) { float v = td[b * SS + j]; ss += v * v; }
#pragma unroll
    for (int o = 16; o; o >>= 1) ss += __shfl_xor_sync(0xffffffffu, ss, o);
    if (ln == 0) red[wid] = ss;
    __syncthreads();
    if (tid == 0) {
        float t = 0.f;
        for (int k = 0; k < 8; k++) t += red[k];
        bc = 1.f / fmaxf(sqrtf(t), 1e-12f);
    }
    __syncthreads();
    float inv = bc;

    float m = -1e4f;
    for (int j = tid; j < SS; j += 256)
        if (mask[b * SS + j]) m = fmaxf(m, td[b * SS + j] * inv);
#pragma unroll
    for (int o = 16; o; o >>= 1) m = fmaxf(m, __shfl_xor_sync(0xffffffffu, m, o));
    if (ln == 0) red[wid] = m;
    __syncthreads();
    if (tid == 0) {
        float t = -1e4f;
        for (int k = 0; k < 8; k++) t = fmaxf(t, red[k]);
        bc = t;
    }
    __syncthreads();
    float mm = bc;
    __syncthreads();

    float den = 0.f;
    for (int j = tid; j < SS; j += 256)
        if (mask[b * SS + j]) den += expf(td[b * SS + j] * inv - mm);
#pragma unroll
    for (int o = 16; o; o >>= 1) den += __shfl_xor_sync(0xffffffffu, den, o);
    if (ln == 0) red[wid] = den;
    __syncthreads();
    if (tid == 0) {
        float t = 0.f;
        for (int k = 0; k < 8; k++) t += red[k];
        bc = 1.f / t;
    }
    __syncthreads();
    float invden = bc;

    for (int j = tid; j < SS; j += 256) {
        float v = mask[b * SS + j] ? expf(td[b * SS + j] * inv - mm) * invden : 0.f;
        g_tdsm[b * SS + j] = v;
    }
}

// ---------------- attention with distance decay ----------------
// grid (S/16, H, B); 8 warps; 2 blocks/SM (16 warps/SM = 4/SMSP).
// 2-D warp partition: warp w owns row-group g=w&3 (4 rows) x j-half=w>>2
// (2 of 4 chunks per tile) in QK and PV -> kt/kv loads halved per block.
// Scores/probs quad-packed fp32: scq[g][SIDX(j)*4 + r%4]. Softmax: 2 rows
// per warp, in-place, register-resident. PV partials combined via smem.
__global__ void __launch_bounds__(ATHR, 2) attn_kernel(const int* __restrict__ mask,
                                                       const float* __restrict__ gammas,
                                                       float* __restrict__ out)
{
    extern __shared__ float sm[];
    float* kt   = sm;                        // 128*66 = 8448
    float* scq  = kt + 128 * 66;             // 4 groups * 4224 = 16896
    float* qs   = scq + 4 * 4224;            // 16*64 = 1024
    float* tdsT = qs + TIQ * 64;             // 1024 (bit-transposed)
    float* sums = tdsT + 1024;               // 16
    unsigned* mbits = (unsigned*)(sums + 16);  // 32 words

    const int tid  = threadIdx.x;
    const int w    = tid >> 5, lane = tid & 31;
    const int i0   = blockIdx.x * TIQ;
    const int h    = blockIdx.y;
    const int b    = blockIdx.z;
    const int g    = w & 3;        // row-group (4 rows)
    const int half = w >> 2;       // j-half (chunks 2*half, 2*half+1 per tile)

    // mask bits via ballot
    for (int base = tid; base < SS; base += ATHR) {
        int mv = mask[b * SS + base];
        unsigned bal = __ballot_sync(0xffffffffu, mv != 0);
        if (lane == 0) mbits[base >> 5] = bal;
    }
    // tds bit-transposed: tdsT[(j&31)<<5 | j>>5] = tdsm[j]
    for (int j = tid; j < SS; j += ATHR)
        tdsT[((j & 31) << 5) | (j >> 5)] = g_tdsm[b * SS + j];
    for (int idx = tid; idx < TIQ * 32; idx += ATHR) {
        int r = idx >> 5, dp = idx & 31;
        *(float2*)&qs[r * 64 + 2 * dp] =
            *(const float2*)(g_mq + (size_t)(b * SS + i0 + r) * AHC + h * DD + 2 * dp);
    }
    float gv = gammas[h];
    float gamma = -(gv > 20.f ? gv : log1pf(expf(gv)));   // -softplus

    // ---- QK: 4 rows x 64 j (2 chunks) per warp per tile ----
    for (int jt = 0; jt < 8; jt++) {
        __syncthreads();
        for (int idx = tid; idx < 4096; idx += ATHR) {
            int r = idx >> 5, dp = idx & 31;
            *(float2*)&kt[r * 66 + 2 * dp] =
                *(const float2*)(g_mk + (size_t)(b * SS + jt * 128 + r) * AHC + h * DD + 2 * dp);
        }
        __syncthreads();
        ull acc[4][2];
#pragma unroll
        for (int rr = 0; rr < 4; rr++) { acc[rr][0] = 0ull; acc[rr][1] = 0ull; }
#pragma unroll
        for (int dp = 0; dp < 32; dp++) {
            ull k0 = *(const ull*)&kt[(half * 64 + lane     ) * 66 + 2 * dp];
            ull k1 = *(const ull*)&kt[(half * 64 + 32 + lane) * 66 + 2 * dp];
#pragma unroll
            for (int rr = 0; rr < 4; rr++) {
                ull q2 = *(const ull*)&qs[(g * 4 + rr) * 64 + 2 * dp];
                ffma2(acc[rr][0], q2, k0);
                ffma2(acc[rr][1], q2, k1);
            }
        }
#pragma unroll
        for (int cc = 0; cc < 2; cc++) {
            int j = jt * 128 + (half * 2 + cc) * 32 + lane;
            float4 sv4;
            float lo, hi;
            unpack2(lo, hi, acc[0][cc]); sv4.x = (lo + hi) * 0.125f;
            unpack2(lo, hi, acc[1][cc]); sv4.y = (lo + hi) * 0.125f;
            unpack2(lo, hi, acc[2][cc]); sv4.z = (lo + hi) * 0.125f;
            unpack2(lo, hi, acc[3][cc]); sv4.w = (lo + hi) * 0.125f;
            *(float4*)&scq[g * 4224 + (j + (j >> 5)) * 4] = sv4;
        }
    }
    __syncthreads();   // all scores visible before cross-warp softmax reads

    // ---- softmax / distance-decay: rows 2w, 2w+1; j = lane*32+c ----
    const unsigned mrow = mbits[lane];
#pragma unroll
    for (int rr2 = 0; rr2 < 2; rr2++) {
        const int r = 2 * w + rr2;
        const int i = i0 + r;
        float* base = scq + (r >> 2) * 4224;
        const int rq = r & 3;
        float sv[32];
#pragma unroll
        for (int c = 0; c < 32; c++) sv[c] = base[(lane * 33 + c) * 4 + rq];

        // pass 1: masked max
        float m1 = -3e38f;
#pragma unroll
        for (int c = 0; c < 32; c++)
            if ((mrow >> c) & 1) m1 = fmaxf(m1, sv[c]);
#pragma unroll
        for (int o = 16; o; o >>= 1) m1 = fmaxf(m1, __shfl_xor_sync(0xffffffffu, m1, o));

        // pass 2: p ~ exp * mask, inclusive cumsum
        float cuml[32];
        float run = 0.f;
#pragma unroll
        for (int c = 0; c < 32; c++) {
            float p = ((mrow >> c) & 1) ? expf(sv[c] - m1) : 0.f;
            run += p;
            cuml[c] = run;
        }
        float v = run;
#pragma unroll
        for (int o = 1; o < 32; o <<= 1) {
            float t = __shfl_up_sync(0xffffffffu, v, o);
            if (lane >= o) v += t;
        }
        float total = __shfl_sync(0xffffffffu, v, 31);
        float off = v - run;
        float invtot = 1.f / fmaxf(total, 1e-30f);

        // pass 3: total_effect, modified scores, max
        float m2 = -3e38f;
#pragma unroll
        for (int c = 0; c < 32; c++) {
            int j = lane * 32 + c;
            float s2;
            if ((mrow >> c) & 1) {
                float cum = cuml[c] + off;
                float pos = fabsf((float)(j - i));
                float rem = (total - cum) * invtot;
                float ds = sqrtf(fmaxf(rem * pos, 0.f));
                float te = expf(gamma * ds);
                te = fminf(fmaxf(te, 1e-5f), 1e5f);
                if (j < i) te -= tdsT[(c << 5) | lane];
                s2 = sv[c] * te;
            } else {
                s2 = -1e8f;
            }
            sv[c] = s2;
            m2 = fmaxf(m2, s2);
        }
#pragma unroll
        for (int o = 16; o; o >>= 1) m2 = fmaxf(m2, __shfl_xor_sync(0xffffffffu, m2, o));

        // pass 4: exp + sum, write probs back in place
        float sum2 = 0.f;
#pragma unroll
        for (int c = 0; c < 32; c++) {
            float e = expf(sv[c] - m2);
            base[(lane * 33 + c) * 4 + rq] = e;
            sum2 += e;
        }
#pragma unroll
        for (int o = 16; o; o >>= 1) sum2 += __shfl_xor_sync(0xffffffffu, sum2, o);
        if (lane == 0) sums[r] = 1.f / sum2;
    }

    // ---- PV: 4 rows x 64 j per warp per tile; probs via uniform LDS.128 ----
    ull acc0 = 0ull, acc1 = 0ull, acc2 = 0ull, acc3 = 0ull;
    const float* pbase = scq + g * 4224;
    for (int jt = 0; jt < 8; jt++) {
        __syncthreads();   // first iter also fences softmax writes
        for (int idx = tid; idx < 4096; idx += ATHR) {
            int r = idx >> 5, dp = idx & 31;
            *(float2*)&kt[r * 66 + 2 * dp] =
                *(const float2*)(g_mv + (size_t)(b * SS + jt * 128 + r) * AHC + h * DD + 2 * dp);
        }
        __syncthreads();
        int jb = jt * 128 + half * 64;
#pragma unroll 8
        for (int q = 0; q < 64; q++) {
            int j = jb + q;
            float4 pr = *(const float4*)&pbase[(j + (j >> 5)) * 4];
            ull kv = *(const ull*)&kt[(half * 64 + q) * 66 + 2 * lane];
            ffma2(acc0, pack2(pr.x, pr.x), kv);
            ffma2(acc1, pack2(pr.y, pr.y), kv);
            ffma2(acc2, pack2(pr.z, pr.z), kv);
            ffma2(acc3, pack2(pr.w, pr.w), kv);
        }
    }

    // ---- combine j-halves (reuse scq as scratch) and write out ----
    __syncthreads();
    float* comb = scq;   // 8 warps * 4 rows * 64 floats = 2048
    {
        float lo, hi;
        unpack2(lo, hi, acc0); *(float2*)&comb[(w * 4 + 0) * 64 + 2 * lane] = make_float2(lo, hi);
        unpack2(lo, hi, acc1); *(float2*)&comb[(w * 4 + 1) * 64 + 2 * lane] = make_float2(lo, hi);
        unpack2(lo, hi, acc2); *(float2*)&comb[(w * 4 + 2) * 64 + 2 * lane] = make_float2(lo, hi);
        unpack2(lo, hi, acc3); *(float2*)&comb[(w * 4 + 3) * 64 + 2 * lane] = make_float2(lo, hi);
    }
    __syncthreads();
    if (w < 4) {
#pragma unroll
        for (int rr = 0; rr < 4; rr++) {
            int r = w * 4 + rr;
            float2 a0 = *(const float2*)&comb[(w * 4 + rr) * 64 + 2 * lane];
            float2 a1 = *(const float2*)&comb[((w + 4) * 4 + rr) * 64 + 2 * lane];
            float iv = sums[r];
            size_t ob = (size_t)(b * SS + i0 + r) * OW + h * DD;
            *(float2*)(out + ob + 2 * lane) =
                make_float2((a0.x + a1.x) * iv, (a0.y + a1.y) * iv);
        }
    }
}

// ---------------- launch ----------------
extern "C" void kernel_launch(void* const* d_in, const int* in_sizes, int n_in,
                              void* d_out, int out_size)
{
    const float* Q      = (const float*)d_in[0];
    const float* Kin    = (const float*)d_in[1];
    const float* V      = (const float*)d_in[2];
    const float* td     = (const float*)d_in[3];
    const int*   mask   = (const int*)  d_in[4];
    const float* Wq     = (const float*)d_in[5];
    const float* Wk     = (const float*)d_in[6];
    const float* Wv     = (const float*)d_in[7];
    const float* dw_w   = (const float*)d_in[8];
    const float* pw_w   = (const float*)d_in[9];
    const float* sep_b  = (const float*)d_in[10];
    const float* ck_W   = (const float*)d_in[11];
    const float* ck_b   = (const float*)d_in[12];
    const float* co_W   = (const float*)d_in[13];
    const float* co_b   = (const float*)d_in[14];
    const float* gammas = (const float*)d_in[15];
    float* out = (float*)d_out;

    float *p_mq, *p_mk, *p_mv, *p_co, *p_mkc, *p_dwt, *p_ckp;
    cudaGetSymbolAddress((void**)&p_mq,  g_mq);
    cudaGetSymbolAddress((void**)&p_mk,  g_mk);
    cudaGetSymbolAddress((void**)&p_mv,  g_mv);
    cudaGetSymbolAddress((void**)&p_co,  g_co);
    cudaGetSymbolAddress((void**)&p_mkc, g_mkc);
    cudaGetSymbolAddress((void**)&p_dwt, g_dwt);
    cudaGetSymbolAddress((void**)&p_ckp, g_ckp);

    const int M = BB * SS;

    // launch order arranged so attn_kernel is the 4th launch (ncu captures #4)
    tdsm_kernel<<<BB, 256>>>(td, mask);                                             // 1
    gemm_fused<<<dim3(M / 128, AHC / 64, 4), 256>>>(Q, Kin, V, Wq, Wk, Wv,          // 2
                                                    co_W, co_b, p_mq, p_mk, p_mv, p_co);
    dw_kernel<<<BB * SS, 256>>>(Kin, dw_w);                                         // 3

    int smem = (128 * 66 + 4 * 4224 + TIQ * 64 + 1024 + 16 + 32) * (int)sizeof(float);
    cudaFuncSetAttribute(attn_kernel, cudaFuncAttributeMaxDynamicSharedMemorySize, smem);
    attn_kernel<<<dim3(SS / TIQ, HH, BB), ATHR, smem>>>(mask, gammas, out);         // 4

    gemm_pw<<<dim3(M / 128, AHC / 64), 256>>>(p_dwt, pw_w, sep_b, p_mkc);           // 5
    gemm_ck<<<dim3(M / 128, 1, CKZ), 256>>>(p_mkc, p_mq, ck_W, ck_b, p_ckp);        // 6
    cksm_kernel<<<(BB * SS * HH + 255) / 256, 256>>>();                             // 7
    conv_out_kernel<<<BB * SS, 128>>>(out);                                         // 8
}

// round 9
// speedup vs baseline: 1.2513x; 1.0344x over previous
#include <cuda_runtime.h>
#include <math.h>

#define BB   4
#define SS   1024
#define HIDC 768
#define HH   6
#define DD   64
#define AHC  384
#define KSC  9
#define PADC 4
#define OW   768   // output width = 2*AH
#define CKN  54    // H*KS
#define CKZ  6     // split-K factor for ck GEMM

typedef unsigned long long ull;

// ---------------- f32x2 packed helpers ----------------
__device__ __forceinline__ void ffma2(ull& d, ull a, ull b) {
    asm("fma.rn.f32x2 %0, %1, %2, %3;" : "=l"(d) : "l"(a), "l"(b), "l"(d));
}
__device__ __forceinline__ ull pack2(float lo, float hi) {
    ull r; asm("mov.b64 %0, {%1, %2};" : "=l"(r) : "f"(lo), "f"(hi)); return r;
}
__device__ __forceinline__ void unpack2(float& lo, float& hi, ull v) {
    asm("mov.b64 {%0, %1}, %2;" : "=f"(lo), "=f"(hi) : "l"(v));
}

// ---------------- scratch (device globals: no allocations allowed) ----------------
__device__ float g_mq [BB*SS*AHC];
__device__ float g_mk [BB*SS*AHC];
__device__ float g_mv [BB*SS*AHC];
__device__ float g_co [BB*SS*AHC];
__device__ float g_mkc[BB*SS*AHC];
__device__ float g_dwt[BB*SS*HIDC];
__device__ float g_ck [BB*SS*CKN];
__device__ float g_ckp[CKZ*BB*SS*CKN];   // split-K partials for ck logits
__device__ float g_tdsm[BB*SS];
__device__ float g_sc [(size_t)BB*HH*SS*SS];   // scores / probs (100 MB)

// ---------------- GEMM core: C[M,N] = scale*(A@B) (+bias), 128x64 tile, f32x2 ----------------
// BT=false: B is [K,N]-style row-major with row stride ldb.
// BT=true : B is [N,K]-style row-major with row stride ldb (C = A @ B^T).
template<bool BT, bool BIAS, bool NGUARD, bool AMUL>
__device__ __forceinline__ void gemm_core(const float* __restrict__ A,
                                          const float* __restrict__ A2,
                                          const float* __restrict__ Bm,
                                          const float* __restrict__ bias,
                                          float* __restrict__ C,
                                          int N, int m0, int n0,
                                          int kBeg, int kEnd,
                                          int lda, int ldb, int ldc, float scale)
{
    __shared__ float As[16][128];
    __shared__ float Bs[16][64];
    const int tid = threadIdx.x;
    const int ty = tid >> 4, tx = tid & 15;
    const int lr = tid >> 1, lk = (tid & 1) * 8;

    ull acc[8][2];
#pragma unroll
    for (int i = 0; i < 8; i++) { acc[i][0] = 0ull; acc[i][1] = 0ull; }

    for (int k0 = kBeg; k0 < kEnd; k0 += 16) {
        {
            const float* ap = A + (size_t)(m0 + lr) * lda + k0 + lk;
            float4 a0 = *(const float4*)(ap);
            float4 a1 = *(const float4*)(ap + 4);
            if (AMUL) {
                const float* a2p = A2 + (size_t)(m0 + lr) * lda + k0 + lk;
                float4 m0v = *(const float4*)(a2p);
                float4 m1v = *(const float4*)(a2p + 4);
                a0.x *= m0v.x; a0.y *= m0v.y; a0.z *= m0v.z; a0.w *= m0v.w;
                a1.x *= m1v.x; a1.y *= m1v.y; a1.z *= m1v.z; a1.w *= m1v.w;
            }
            As[lk + 0][lr] = a0.x; As[lk + 1][lr] = a0.y;
            As[lk + 2][lr] = a0.z; As[lk + 3][lr] = a0.w;
            As[lk + 4][lr] = a1.x; As[lk + 5][lr] = a1.y;
            As[lk + 6][lr] = a1.z; As[lk + 7][lr] = a1.w;
        }
        if (!BT) {
            int bk = tid >> 4, bn = (tid & 15) * 4;
            if (!NGUARD) {
                float4 bv = *(const float4*)(Bm + (size_t)(k0 + bk) * ldb + n0 + bn);
                Bs[bk][bn + 0] = bv.x; Bs[bk][bn + 1] = bv.y;
                Bs[bk][bn + 2] = bv.z; Bs[bk][bn + 3] = bv.w;
            } else {
#pragma unroll
                for (int j = 0; j < 4; j++) {
                    int n = n0 + bn + j;
                    Bs[bk][bn + j] = (n < N) ? Bm[(size_t)(k0 + bk) * ldb + n] : 0.f;
                }
            }
        } else {
            int bn = tid >> 2, bkk = (tid & 3) * 4;
            float4 bv = *(const float4*)(Bm + (size_t)(n0 + bn) * ldb + k0 + bkk);
            Bs[bkk + 0][bn] = bv.x; Bs[bkk + 1][bn] = bv.y;
            Bs[bkk + 2][bn] = bv.z; Bs[bkk + 3][bn] = bv.w;
        }
        __syncthreads();
#pragma unroll
        for (int k = 0; k < 16; k++) {
            float4 aA = *(const float4*)&As[k][ty * 8];
            float4 aB = *(const float4*)&As[k][ty * 8 + 4];
            ull b01 = *(const ull*)&Bs[k][tx * 4];
            ull b23 = *(const ull*)&Bs[k][tx * 4 + 2];
            ull ap;
            ap = pack2(aA.x, aA.x); ffma2(acc[0][0], ap, b01); ffma2(acc[0][1], ap, b23);
            ap = pack2(aA.y, aA.y); ffma2(acc[1][0], ap, b01); ffma2(acc[1][1], ap, b23);
            ap = pack2(aA.z, aA.z); ffma2(acc[2][0], ap, b01); ffma2(acc[2][1], ap, b23);
            ap = pack2(aA.w, aA.w); ffma2(acc[3][0], ap, b01); ffma2(acc[3][1], ap, b23);
            ap = pack2(aB.x, aB.x); ffma2(acc[4][0], ap, b01); ffma2(acc[4][1], ap, b23);
            ap = pack2(aB.y, aB.y); ffma2(acc[5][0], ap, b01); ffma2(acc[5][1], ap, b23);
            ap = pack2(aB.z, aB.z); ffma2(acc[6][0], ap, b01); ffma2(acc[6][1], ap, b23);
            ap = pack2(aB.w, aB.w); ffma2(acc[7][0], ap, b01); ffma2(acc[7][1], ap, b23);
        }
        __syncthreads();
    }
#pragma unroll
    for (int i = 0; i < 8; i++) {
        int m = m0 + ty * 8 + i;
#pragma unroll
        for (int p = 0; p < 2; p++) {
            float lo, hi; unpack2(lo, hi, acc[i][p]);
            int n = n0 + tx * 4 + 2 * p;
            if (!NGUARD || n < N) {
                float v = lo * scale; if (BIAS) v += bias[n];
                C[(size_t)m * ldc + n] = v;
            }
            if (!NGUARD || n + 1 < N) {
                float v = hi * scale; if (BIAS) v += bias[n + 1];
                C[(size_t)m * ldc + n + 1] = v;
            }
        }
    }
}

// fused 4-way projection GEMM: z selects (A, B, bias, C)
__global__ void __launch_bounds__(256) gemm_fused(const float* __restrict__ Q,
                                                  const float* __restrict__ Kin,
                                                  const float* __restrict__ V,
                                                  const float* __restrict__ Wq,
                                                  const float* __restrict__ Wk,
                                                  const float* __restrict__ Wv,
                                                  const float* __restrict__ coW,
                                                  const float* __restrict__ cob,
                                                  float* __restrict__ mq,
                                                  float* __restrict__ mk,
                                                  float* __restrict__ mv,
                                                  float* __restrict__ co)
{
    int m0 = blockIdx.x * 128, n0 = blockIdx.y * 64;
    switch (blockIdx.z) {
    case 0: gemm_core<false,false,false,false>(Q,   nullptr, Wq,  nullptr, mq, AHC, m0, n0, 0, HIDC, HIDC, AHC, AHC, 1.f); break;
    case 1: gemm_core<false,false,false,false>(Kin, nullptr, Wk,  nullptr, mk, AHC, m0, n0, 0, HIDC, HIDC, AHC, AHC, 1.f); break;
    case 2: gemm_core<false,false,false,false>(V,   nullptr, Wv,  nullptr, mv, AHC, m0, n0, 0, HIDC, HIDC, AHC, AHC, 1.f); break;
    default:gemm_core<false,true, false,false>(V,   nullptr, coW, cob,     co, AHC, m0, n0, 0, HIDC, HIDC, AHC, AHC, 1.f); break;
    }
}

// pointwise conv GEMM: mkc = dwt @ pw_w^T + sep_b
__global__ void __launch_bounds__(256) gemm_pw(const float* __restrict__ dwt,
                                               const float* __restrict__ pw,
                                               const float* __restrict__ sb,
                                               float* __restrict__ mkc)
{
    gemm_core<true, true, false, false>(dwt, nullptr, pw, sb, mkc,
                                        AHC, blockIdx.x * 128, blockIdx.y * 64,
                                        0, HIDC, HIDC, HIDC, AHC, 1.f);
}

// ck logits GEMM, split-K x CKZ
__global__ void __launch_bounds__(256) gemm_ck(const float* __restrict__ mkc,
                                               const float* __restrict__ mq,
                                               const float* __restrict__ ckW,
                                               const float* __restrict__ ckb,
                                               float* __restrict__ ckp)
{
    int z = blockIdx.z;
    const int KS_ = AHC / CKZ;   // 64
    float* Cz = ckp + (size_t)z * (BB * SS * CKN);
    if (z == 0)
        gemm_core<false, true,  true, true>(mkc, mq, ckW, ckb, Cz,
                                            CKN, blockIdx.x * 128, 0, 0, KS_,
                                            AHC, CKN, CKN, 1.f);
    else
        gemm_core<false, false, true, true>(mkc, mq, ckW, nullptr, Cz,
                                            CKN, blockIdx.x * 128, 0, z * KS_, z * KS_ + KS_,
                                            AHC, CKN, CKN, 1.f);
}

// QK GEMM: scores[b,h][i][j] = (mq_i . mk_j) / 8
__global__ void __launch_bounds__(256) gemm_qk(const float* __restrict__ mq,
                                               const float* __restrict__ mk,
                                               float* __restrict__ sc)
{
    int z = blockIdx.z;             // b*HH + h
    int b = z / HH, h = z % HH;
    const float* Aq = mq + (size_t)(b * SS) * AHC + h * DD;
    const float* Bk = mk + (size_t)(b * SS) * AHC + h * DD;
    float* Cz = sc + (size_t)z * SS * SS;
    gemm_core<true, false, false, false>(Aq, nullptr, Bk, nullptr, Cz,
                                         SS, blockIdx.x * 128, blockIdx.y * 64,
                                         0, DD, AHC, AHC, SS, 0.125f);
}

// PV GEMM: out[b][i][h*DD+d] = sum_j probs[i][j] * mv[j][d]
__global__ void __launch_bounds__(256) gemm_pv(const float* __restrict__ sc,
                                               const float* __restrict__ mv,
                                               float* __restrict__ out)
{
    int z = blockIdx.z;
    int b = z / HH, h = z % HH;
    const float* Ap = sc + (size_t)z * SS * SS;
    const float* Bv = mv + (size_t)(b * SS) * AHC + h * DD;
    float* Cz = out + (size_t)(b * SS) * OW + h * DD;
    gemm_core<false, false, false, false>(Ap, nullptr, Bv, nullptr, Cz,
                                          64, blockIdx.x * 128, 0,
                                          0, SS, SS, AHC, OW, 1.f);
}

// ---------------- softmax / distance-decay over gmem scores, in-place ----------------
// grid (S/8, H, B); 8 warps x 1 row. Row staged smem-pitched (j + (j>>5)),
// conflict-free both coalesced (gmem side) and per-lane (j = lane*32+c).
__global__ void __launch_bounds__(256) softmax_kernel(const int* __restrict__ mask,
                                                      const float* __restrict__ gammas,
                                                      float* __restrict__ sc)
{
    __shared__ float srows[8 * 1056];
    __shared__ float tdsT[1024];
    __shared__ unsigned mbits[32];

    const int tid  = threadIdx.x;
    const int w    = tid >> 5, lane = tid & 31;
    const int h    = blockIdx.y;
    const int b    = blockIdx.z;
    const int i    = blockIdx.x * 8 + w;

    for (int base = tid; base < SS; base += 256) {
        int mv = mask[b * SS + base];
        unsigned bal = __ballot_sync(0xffffffffu, mv != 0);
        if (lane == 0) mbits[base >> 5] = bal;
    }
    for (int j = tid; j < SS; j += 256)
        tdsT[((j & 31) << 5) | (j >> 5)] = g_tdsm[b * SS + j];
    __syncthreads();

    float gv = gammas[h];
    float gamma = -(gv > 20.f ? gv : log1pf(expf(gv)));   // -softplus

    float* srow = srows + w * 1056;
    float* grow = sc + ((size_t)((b * HH + h)) * SS + i) * SS;

    // stage row: coalesced LDG.128 -> pitched smem (conflict-free)
#pragma unroll
    for (int t = 0; t < 8; t++) {
        float4 v = *(const float4*)(grow + t * 128 + lane * 4);
        int a = t * 132 + lane * 4 + (lane >> 3);
        srow[a] = v.x; srow[a + 1] = v.y; srow[a + 2] = v.z; srow[a + 3] = v.w;
    }
    __syncwarp();

    const unsigned mrow = mbits[lane];
    float sv[32];
#pragma unroll
    for (int c = 0; c < 32; c++) sv[c] = srow[lane * 33 + c];

    // pass 1: masked max
    float m1 = -3e38f;
#pragma unroll
    for (int c = 0; c < 32; c++)
        if ((mrow >> c) & 1) m1 = fmaxf(m1, sv[c]);
#pragma unroll
    for (int o = 16; o; o >>= 1) m1 = fmaxf(m1, __shfl_xor_sync(0xffffffffu, m1, o));

    // pass 2: p ~ exp * mask, inclusive cumsum
    float cuml[32];
    float run = 0.f;
#pragma unroll
    for (int c = 0; c < 32; c++) {
        float p = ((mrow >> c) & 1) ? expf(sv[c] - m1) : 0.f;
        run += p;
        cuml[c] = run;
    }
    float v = run;
#pragma unroll
    for (int o = 1; o < 32; o <<= 1) {
        float t = __shfl_up_sync(0xffffffffu, v, o);
        if (lane >= o) v += t;
    }
    float total = __shfl_sync(0xffffffffu, v, 31);
    float off = v - run;
    float invtot = 1.f / fmaxf(total, 1e-30f);

    // pass 3: total_effect, modified scores, max
    float m2 = -3e38f;
#pragma unroll
    for (int c = 0; c < 32; c++) {
        int j = lane * 32 + c;
        float s2;
        if ((mrow >> c) & 1) {
            float cum = cuml[c] + off;
            float pos = fabsf((float)(j - i));
            float rem = (total - cum) * invtot;
            float ds = sqrtf(fmaxf(rem * pos, 0.f));
            float te = expf(gamma * ds);
            te = fminf(fmaxf(te, 1e-5f), 1e5f);
            if (j < i) te -= tdsT[(c << 5) | lane];
            s2 = sv[c] * te;
        } else {
            s2 = -1e8f;
        }
        sv[c] = s2;
        m2 = fmaxf(m2, s2);
    }
#pragma unroll
    for (int o = 16; o; o >>= 1) m2 = fmaxf(m2, __shfl_xor_sync(0xffffffffu, m2, o));

    // pass 4: exp + sum, normalize, stage back
    float sum2 = 0.f;
#pragma unroll
    for (int c = 0; c < 32; c++) {
        float e = expf(sv[c] - m2);
        sv[c] = e;
        sum2 += e;
    }
#pragma unroll
    for (int o = 16; o; o >>= 1) sum2 += __shfl_xor_sync(0xffffffffu, sum2, o);
    float invs = 1.f / sum2;
#pragma unroll
    for (int c = 0; c < 32; c++) srow[lane * 33 + c] = sv[c] * invs;
    __syncwarp();

    // write back coalesced
#pragma unroll
    for (int t = 0; t < 8; t++) {
        int a = t * 132 + lane * 4 + (lane >> 3);
        float4 o4;
        o4.x = srow[a]; o4.y = srow[a + 1]; o4.z = srow[a + 2]; o4.w = srow[a + 3];
        *(float4*)(grow + t * 128 + lane * 4) = o4;
    }
}

// ck: sum CKZ partials, softmax over KS=9, write g_ck
__global__ void __launch_bounds__(256) cksm_kernel()
{
    int row = blockIdx.x * 256 + threadIdx.x;     // BB*SS*HH rows
    if (row >= BB * SS * HH) return;
    const size_t R = (size_t)BB * SS * CKN;
    const float* p0 = g_ckp + (size_t)row * KSC;
    float v[KSC];
    float m = -3e38f;
#pragma unroll
    for (int k = 0; k < KSC; k++) {
        float s = 0.f;
#pragma unroll
        for (int z = 0; z < CKZ; z++) s += p0[z * R + k];
        v[k] = s;
        m = fmaxf(m, s);
    }
    float sum = 0.f;
#pragma unroll
    for (int k = 0; k < KSC; k++) { v[k] = expf(v[k] - m); sum += v[k]; }
    float invs = 1.f / sum;
    float* o = g_ck + (size_t)row * KSC;
#pragma unroll
    for (int k = 0; k < KSC; k++) o[k] = v[k] * invs;
}

// ---------------- depthwise conv over sequence (kernel 9, pad 4) ----------------
__global__ void __launch_bounds__(256) dw_kernel(const float* __restrict__ Kin,
                                                 const float* __restrict__ dw_w)
{
    int bs = blockIdx.x;              // b*S + s
    int b = bs >> 10, s = bs & 1023;
    for (int c = threadIdx.x; c < HIDC; c += 256) {
        float acc = 0.f;
#pragma unroll
        for (int k = 0; k < KSC; k++) {
            int sr = s + k - PADC;
            if (sr >= 0 && sr < SS)
                acc += Kin[(size_t)(b * SS + sr) * HIDC + c] * dw_w[c * KSC + k];
        }
        g_dwt[(size_t)bs * HIDC + c] = acc;
    }
}

// ---------------- conv_out: sliding-window gather of co weighted by ck ----------------
__global__ void __launch_bounds__(128) conv_out_kernel(float* __restrict__ out)
{
    int bs = blockIdx.x;
    int b = bs >> 10, s = bs & 1023;
    __shared__ float cks[CKN];
    if (threadIdx.x < CKN) cks[threadIdx.x] = g_ck[(size_t)bs * CKN + threadIdx.x];
    __syncthreads();
    for (int a = threadIdx.x; a < AHC; a += 128) {
        int h = a >> 6;
        float acc = 0.f;
#pragma unroll
        for (int k = 0; k < KSC; k++) {
            int sr = s + k - PADC;
            if (sr >= 0 && sr < SS)
                acc += g_co[(size_t)(b * SS + sr) * AHC + a] * cks[h * KSC + k];
        }
        out[(size_t)bs * OW + AHC + a] = acc;
    }
}

// ---------------- td softmax (independent of head and query row) ----------------
__global__ void __launch_bounds__(256) tdsm_kernel(const float* __restrict__ td,
                                                   const int* __restrict__ mask)
{
    __shared__ float red[8];
    __shared__ float bc;
    int b = blockIdx.x, tid = threadIdx.x;
    int wid = tid >> 5, ln = tid & 31;

    float ss = 0.f;
    for (int j = tid; j < SS; j += 256) { float v = td[b * SS + j]; ss += v * v; }
#pragma unroll
    for (int o = 16; o; o >>= 1) ss += __shfl_xor_sync(0xffffffffu, ss, o);
    if (ln == 0) red[wid] = ss;
    __syncthreads();
    if (tid == 0) {
        float t = 0.f;
        for (int k = 0; k < 8; k++) t += red[k];
        bc = 1.f / fmaxf(sqrtf(t), 1e-12f);
    }
    __syncthreads();
    float inv = bc;

    float m = -1e4f;
    for (int j = tid; j < SS; j += 256)
        if (mask[b * SS + j]) m = fmaxf(m, td[b * SS + j] * inv);
#pragma unroll
    for (int o = 16; o; o >>= 1) m = fmaxf(m, __shfl_xor_sync(0xffffffffu, m, o));
    if (ln == 0) red[wid] = m;
    __syncthreads();
    if (tid == 0) {
        float t = -1e4f;
        for (int k = 0; k < 8; k++) t = fmaxf(t, red[k]);
        bc = t;
    }
    __syncthreads();
    float mm = bc;
    __syncthreads();

    float den = 0.f;
    for (int j = tid; j < SS; j += 256)
        if (mask[b * SS + j]) den += expf(td[b * SS + j] * inv - mm);
#pragma unroll
    for (int o = 16; o; o >>= 1) den += __shfl_xor_sync(0xffffffffu, den, o);
    if (ln == 0) red[wid] = den;
    __syncthreads();
    if (tid == 0) {
        float t = 0.f;
        for (int k = 0; k < 8; k++) t += red[k];
        bc = 1.f / t;
    }
    __syncthreads();
    float invden = bc;

    for (int j = tid; j < SS; j += 256) {
        float v = mask[b * SS + j] ? expf(td[b * SS + j] * inv - mm) * invden : 0.f;
        g_tdsm[b * SS + j] = v;
    }
}

// ---------------- launch ----------------
extern "C" void kernel_launch(void* const* d_in, const int* in_sizes, int n_in,
                              void* d_out, int out_size)
{
    const float* Q      = (const float*)d_in[0];
    const float* Kin    = (const float*)d_in[1];
    const float* V      = (const float*)d_in[2];
    const float* td     = (const float*)d_in[3];
    const int*   mask   = (const int*)  d_in[4];
    const float* Wq     = (const float*)d_in[5];
    const float* Wk     = (const float*)d_in[6];
    const float* Wv     = (const float*)d_in[7];
    const float* dw_w   = (const float*)d_in[8];
    const float* pw_w   = (const float*)d_in[9];
    const float* sep_b  = (const float*)d_in[10];
    const float* ck_W   = (const float*)d_in[11];
    const float* ck_b   = (const float*)d_in[12];
    const float* co_W   = (const float*)d_in[13];
    const float* co_b   = (const float*)d_in[14];
    const float* gammas = (const float*)d_in[15];
    float* out = (float*)d_out;

    float *p_mq, *p_mk, *p_mv, *p_co, *p_mkc, *p_dwt, *p_ckp, *p_sc;
    cudaGetSymbolAddress((void**)&p_mq,  g_mq);
    cudaGetSymbolAddress((void**)&p_mk,  g_mk);
    cudaGetSymbolAddress((void**)&p_mv,  g_mv);
    cudaGetSymbolAddress((void**)&p_co,  g_co);
    cudaGetSymbolAddress((void**)&p_mkc, g_mkc);
    cudaGetSymbolAddress((void**)&p_dwt, g_dwt);
    cudaGetSymbolAddress((void**)&p_ckp, g_ckp);
    cudaGetSymbolAddress((void**)&p_sc,  g_sc);

    const int M = BB * SS;

    // order: softmax_kernel is the 4th launch (ncu captures #4)
    tdsm_kernel<<<BB, 256>>>(td, mask);                                             // 1
    gemm_fused<<<dim3(M / 128, AHC / 64, 4), 256>>>(Q, Kin, V, Wq, Wk, Wv,          // 2
                                                    co_W, co_b, p_mq, p_mk, p_mv, p_co);
    gemm_qk<<<dim3(SS / 128, SS / 64, BB * HH), 256>>>(p_mq, p_mk, p_sc);           // 3
    softmax_kernel<<<dim3(SS / 8, HH, BB), 256>>>(mask, gammas, p_sc);              // 4
    gemm_pv<<<dim3(SS / 128, 1, BB * HH), 256>>>(p_sc, p_mv, out);                  // 5

    dw_kernel<<<BB * SS, 256>>>(Kin, dw_w);                                         // 6
    gemm_pw<<<dim3(M / 128, AHC / 64), 256>>>(p_dwt, pw_w, sep_b, p_mkc);           // 7
    gemm_ck<<<dim3(M / 128, 1, CKZ), 256>>>(p_mkc, p_mq, ck_W, ck_b, p_ckp);        // 8
    cksm_kernel<<<(BB * SS * HH + 255) / 256, 256>>>();                             // 9
    conv_out_kernel<<<BB * SS, 128>>>(out);                                         // 10
}